// round 16
// baseline (speedup 1.0000x reference)
#include <cuda_runtime.h>
#include <cuda_bf16.h>
#include <math.h>
#include <stdint.h>

#define N_TOK 4096
#define D_MODEL 256
#define H_HEADS 8
#define HD 32
#define QKV_W 768

// ---------------- scratch (device globals; no allocation allowed) ----------
__device__ __nv_bfloat16 g_qkv_bf[N_TOK * QKV_W];      // bf16 q|k|v
__device__ __nv_bfloat16 g_attn_bf[N_TOK * D_MODEL];   // attention out (bf16)
__device__ __nv_bfloat16 g_slots_bf[N_TOK * D_MODEL];
__device__ __nv_bfloat16 g_win_bf[QKV_W * D_MODEL];
__device__ __nv_bfloat16 g_wout_bf[D_MODEL * D_MODEL];

// =================== mma / cp.async / ldmatrix helpers =====================
__device__ __forceinline__ void mma_bf16(float& d0, float& d1, float& d2, float& d3,
                                         uint32_t a0, uint32_t a1, uint32_t a2, uint32_t a3,
                                         uint32_t b0, uint32_t b1) {
    asm volatile("mma.sync.aligned.m16n8k16.row.col.f32.bf16.bf16.f32 "
                 "{%0,%1,%2,%3}, {%4,%5,%6,%7}, {%8,%9}, {%0,%1,%2,%3};"
                 : "+f"(d0), "+f"(d1), "+f"(d2), "+f"(d3)
                 : "r"(a0), "r"(a1), "r"(a2), "r"(a3), "r"(b0), "r"(b1));
}

__device__ __forceinline__ void cp_async16(uint32_t dst, const void* src) {
    asm volatile("cp.async.cg.shared.global [%0], [%1], 16;" :: "r"(dst), "l"(src));
}
__device__ __forceinline__ void cp_commit() {
    asm volatile("cp.async.commit_group;");
}
template <int Nwait>
__device__ __forceinline__ void cp_wait() {
    asm volatile("cp.async.wait_group %0;" :: "n"(Nwait));
}

// transposed 8x8 b16 x4 loads (for V^T fragments)
__device__ __forceinline__ void ldsm_x4_trans(uint32_t& r0, uint32_t& r1,
                                              uint32_t& r2, uint32_t& r3, uint32_t addr) {
    asm volatile("ldmatrix.sync.aligned.m8n8.x4.trans.shared.b16 {%0,%1,%2,%3}, [%4];"
                 : "=r"(r0), "=r"(r1), "=r"(r2), "=r"(r3) : "r"(addr));
}

// pack two fp32 into one bf16x2 register (lo -> low half, hi -> high half)
__device__ __forceinline__ uint32_t pack_bf16x2(float lo, float hi) {
    uint32_t r;
    asm("cvt.rn.bf16x2.f32 %0, %1, %2;" : "=r"(r) : "f"(hi), "f"(lo));
    return r;
}

// =================== fp32 -> bf16 conversion (3 arrays, one launch) ========
__global__ void cvt_bf16_kernel(const float* __restrict__ s0, __nv_bfloat16* __restrict__ d0, int n0,
                                const float* __restrict__ s1, __nv_bfloat16* __restrict__ d1, int n1,
                                const float* __restrict__ s2, __nv_bfloat16* __restrict__ d2, int n2) {
    int i = blockIdx.x * blockDim.x + threadIdx.x;  // one float4 per thread
    const float* s;
    __nv_bfloat16* d;
    int off;
    int q0 = n0 >> 2, q1 = q0 + (n1 >> 2), q2 = q1 + (n2 >> 2);
    if (i >= q2) return;
    if (i < q0) { s = s0; d = d0; off = i * 4; }
    else if (i < q1) { s = s1; d = d1; off = (i - q0) * 4; }
    else { s = s2; d = d2; off = (i - q1) * 4; }
    float4 v = *(const float4*)&s[off];
    *(uint32_t*)&d[off] = pack_bf16x2(v.x, v.y);
    *(uint32_t*)&d[off + 2] = pack_bf16x2(v.z, v.w);
}

// ===== bf16 GEMM1: C[M,N] = A[M,K] @ B[N,K]^T + bias, bf16 output ==========
// Block tile 128x64, 8 warps (4x2), warp tile 32x32. BK=64 -> 4 stages,
// depth-2 pipeline, stride-36 smem (conflict-free frags), ~55 KB smem.
#define GBM 128
#define GBN 64
#define GBK 64
#define G1STW 36

__global__ void gemm_bf16_kernel(const __nv_bfloat16* __restrict__ A,
                                 const __nv_bfloat16* __restrict__ B,
                                 const float* __restrict__ bias,
                                 __nv_bfloat16* __restrict__ C,
                                 int M, int N, int K) {
    __shared__ uint32_t As[2 * GBM * G1STW];
    __shared__ uint32_t Bs[2 * GBN * G1STW];

    const int t = threadIdx.x;            // 256 threads
    const int wid = t >> 5;
    const int lane = t & 31;
    const int g = lane >> 2;
    const int tq = lane & 3;
    const int wm = (wid & 3) * 32;
    const int wn = (wid >> 2) * 32;
    const int m0 = blockIdx.y * GBM;
    const int n0 = blockIdx.x * GBN;

    float acc[2][4][4];
#pragma unroll
    for (int mi = 0; mi < 2; mi++)
#pragma unroll
        for (int ni = 0; ni < 4; ni++)
#pragma unroll
            for (int c = 0; c < 4; c++) acc[mi][ni][c] = 0.f;

    const int T = K / GBK;                // 4 stages

    auto issue = [&](int kt, int buf) {
        const __nv_bfloat16* Ab = A + (size_t)m0 * K + kt * GBK;
#pragma unroll
        for (int i = 0; i < 4; i++) {     // A: 128 rows x 8 chunks = 1024
            int fi = t + i * 256;
            int row = fi >> 3, c16 = fi & 7;
            cp_async16((uint32_t)__cvta_generic_to_shared(&As[(buf * GBM + row) * G1STW + c16 * 4]),
                       Ab + (size_t)row * K + c16 * 8);
        }
        const __nv_bfloat16* Bb = B + (size_t)n0 * K + kt * GBK;
#pragma unroll
        for (int i = 0; i < 2; i++) {     // B: 64 rows x 8 chunks = 512
            int fi = t + i * 256;
            int row = fi >> 3, c16 = fi & 7;
            cp_async16((uint32_t)__cvta_generic_to_shared(&Bs[(buf * GBN + row) * G1STW + c16 * 4]),
                       Bb + (size_t)row * K + c16 * 8);
        }
        cp_commit();
    };

    issue(0, 0);
    if (T > 1) issue(1, 1);

    for (int i = 0; i < T; i++) {
        if (i + 1 < T) cp_wait<1>(); else cp_wait<0>();
        __syncthreads();

        const uint32_t* Ab = As + (i & 1) * GBM * G1STW;
        const uint32_t* Bb = Bs + (i & 1) * GBN * G1STW;
#pragma unroll
        for (int ks = 0; ks < 4; ks++) {  // four k16 steps per BK=64
            const int kw = ks * 8;
            uint32_t a[2][4];
#pragma unroll
            for (int mi = 0; mi < 2; mi++) {
                int r0 = wm + mi * 16 + g;
                a[mi][0] = Ab[r0 * G1STW + kw + tq];
                a[mi][1] = Ab[(r0 + 8) * G1STW + kw + tq];
                a[mi][2] = Ab[r0 * G1STW + kw + tq + 4];
                a[mi][3] = Ab[(r0 + 8) * G1STW + kw + tq + 4];
            }
#pragma unroll
            for (int ni = 0; ni < 4; ni++) {
                int bc = wn + ni * 8 + g;
                uint32_t b0 = Bb[bc * G1STW + kw + tq];
                uint32_t b1 = Bb[bc * G1STW + kw + tq + 4];
#pragma unroll
                for (int mi = 0; mi < 2; mi++)
                    mma_bf16(acc[mi][ni][0], acc[mi][ni][1], acc[mi][ni][2], acc[mi][ni][3],
                             a[mi][0], a[mi][1], a[mi][2], a[mi][3], b0, b1);
            }
        }
        __syncthreads();
        if (i + 2 < T) issue(i + 2, i & 1);
    }

#pragma unroll
    for (int mi = 0; mi < 2; mi++) {
#pragma unroll
        for (int ni = 0; ni < 4; ni++) {
            int col = n0 + wn + ni * 8 + 2 * tq;
            int r0 = m0 + wm + mi * 16 + g;
            int r1 = r0 + 8;
            float bx = bias[col], by = bias[col + 1];
            *(uint32_t*)&C[(size_t)r0 * N + col] = pack_bf16x2(acc[mi][ni][0] + bx, acc[mi][ni][1] + by);
            *(uint32_t*)&C[(size_t)r1 * N + col] = pack_bf16x2(acc[mi][ni][2] + bx, acc[mi][ni][3] + by);
        }
    }
}

// ====== fused GEMM2 + bias + residual + LayerNorm (R13 config) =============
#define G2BM 32
#define G2BN 256
#define G2BK 64
#define G2STW 36                                      // 32 data words + 4 pad
#define G2AB (2 * G2BM * G2STW + 2 * G2BN * G2STW)    // 20736 words
#define G2RES G2AB                                     // resid: 8192 words
#define G2PAR (G2AB + G2BM * 256)                      // bias|gamma|beta: 768
#define G2WORDS (G2PAR + 768)                          // 29696 words (~116 KB)

__global__ void gemm2_ln_kernel(const __nv_bfloat16* __restrict__ A,
                                const __nv_bfloat16* __restrict__ B,
                                const float* __restrict__ bias,
                                const float* __restrict__ resid,
                                const float* __restrict__ gamma,
                                const float* __restrict__ beta,
                                float* __restrict__ out) {
    extern __shared__ uint32_t sm[];
    uint32_t* As = sm;                      // [2][G2BM][G2STW]
    uint32_t* Bs = sm + 2 * G2BM * G2STW;   // [2][G2BN][G2STW]
    float* Rs = (float*)(sm + G2RES);       // [32][256] residual
    float* Pv = (float*)(sm + G2PAR);       // bias[256] gamma[256] beta[256]
    float* Cs = (float*)sm;                 // epilogue alias, stride 264

    const int t = threadIdx.x;              // 512 threads
    const int wid = t >> 5;                 // 0..15
    const int lane = t & 31;
    const int g = lane >> 2;
    const int tq = lane & 3;
    const int wm = (wid & 1) * 16;
    const int wn = (wid >> 1) * 32;
    const int m0 = blockIdx.x * G2BM;
    const int K = 256, T = 4;               // 4 stages of BK=64

    float acc[4][4];
#pragma unroll
    for (int ni = 0; ni < 4; ni++)
#pragma unroll
        for (int c = 0; c < 4; c++) acc[ni][c] = 0.f;

    auto issue = [&](int kt, int buf) {
        if (t < 256) {                      // A: 32 rows x 8 chunks
            int row = t >> 3, c16 = t & 7;
            cp_async16((uint32_t)__cvta_generic_to_shared(&As[(buf * G2BM + row) * G2STW + c16 * 4]),
                       A + (size_t)(m0 + row) * K + kt * G2BK + c16 * 8);
        }
#pragma unroll
        for (int i = 0; i < 4; i++) {       // B: 256 rows x 8 chunks = 2048
            int fi = t + i * 512;
            int row = fi >> 3, c16 = fi & 7;
            cp_async16((uint32_t)__cvta_generic_to_shared(&Bs[(buf * G2BN + row) * G2STW + c16 * 4]),
                       B + (size_t)row * K + kt * G2BK + c16 * 8);
        }
        // resid rows [kt*8, kt*8+8): 8 rows x 64 chunks = 512 (all threads)
        {
            int rr = kt * 8 + (t >> 6);
            int c4 = t & 63;
            cp_async16((uint32_t)__cvta_generic_to_shared(&Rs[rr * 256 + c4 * 4]),
                       resid + (size_t)(m0 + rr) * 256 + c4 * 4);
        }
        if (kt == 0) {                      // params: 192 chunks
            if (t < 64)
                cp_async16((uint32_t)__cvta_generic_to_shared(&Pv[t * 4]), bias + t * 4);
            else if (t < 128)
                cp_async16((uint32_t)__cvta_generic_to_shared(&Pv[256 + (t - 64) * 4]), gamma + (t - 64) * 4);
            else if (t < 192)
                cp_async16((uint32_t)__cvta_generic_to_shared(&Pv[512 + (t - 128) * 4]), beta + (t - 128) * 4);
        }
        cp_commit();
    };

    issue(0, 0);
    issue(1, 1);

    for (int i = 0; i < T; i++) {
        if (i + 1 < T) cp_wait<1>(); else cp_wait<0>();
        __syncthreads();

        const uint32_t* Ab = As + (i & 1) * G2BM * G2STW;
        const uint32_t* Bb = Bs + (i & 1) * G2BN * G2STW;
#pragma unroll
        for (int ks = 0; ks < 4; ks++) {
            const int kw = ks * 8;
            uint32_t a0 = Ab[(wm + g) * G2STW + kw + tq];
            uint32_t a1 = Ab[(wm + g + 8) * G2STW + kw + tq];
            uint32_t a2 = Ab[(wm + g) * G2STW + kw + tq + 4];
            uint32_t a3 = Ab[(wm + g + 8) * G2STW + kw + tq + 4];
#pragma unroll
            for (int ni = 0; ni < 4; ni++) {
                int bc = wn + ni * 8 + g;
                uint32_t b0 = Bb[bc * G2STW + kw + tq];
                uint32_t b1 = Bb[bc * G2STW + kw + tq + 4];
                mma_bf16(acc[ni][0], acc[ni][1], acc[ni][2], acc[ni][3],
                         a0, a1, a2, a3, b0, b1);
            }
        }
        __syncthreads();
        if (i + 2 < T) issue(i + 2, i & 1);
    }

    // stage acc + bias into smem (full 256-wide rows; aliases AB buffers)
#pragma unroll
    for (int ni = 0; ni < 4; ni++) {
        int col = wn + ni * 8 + 2 * tq;
        float bx = Pv[col], by = Pv[col + 1];
        *(float2*)&Cs[(wm + g) * 264 + col] = make_float2(acc[ni][0] + bx, acc[ni][1] + by);
        *(float2*)&Cs[(wm + g + 8) * 264 + col] = make_float2(acc[ni][2] + bx, acc[ni][3] + by);
    }
    __syncthreads();

    // LayerNorm: warp w handles rows 2w, 2w+1; all operands in smem
#pragma unroll
    for (int rr = wid * 2; rr < wid * 2 + 2; rr++) {
        float v[8], s = 0.f;
#pragma unroll
        for (int k = 0; k < 8; k++) {
            int c = lane + 32 * k;
            v[k] = Cs[rr * 264 + c] + Rs[rr * 256 + c];
            s += v[k];
        }
#pragma unroll
        for (int o = 16; o > 0; o >>= 1) s += __shfl_xor_sync(0xffffffffu, s, o);
        const float mean = s * (1.f / 256.f);
        float sq = 0.f;
#pragma unroll
        for (int k = 0; k < 8; k++) { float d = v[k] - mean; sq += d * d; }
#pragma unroll
        for (int o = 16; o > 0; o >>= 1) sq += __shfl_xor_sync(0xffffffffu, sq, o);
        const float rsig = rsqrtf(sq * (1.f / 256.f) + 1e-5f);
#pragma unroll
        for (int k = 0; k < 8; k++) {
            int c = lane + 32 * k;
            out[(size_t)(m0 + rr) * 256 + c] = (v[k] - mean) * rsig * Pv[256 + c] + Pv[512 + c];
        }
    }
}

// ============== bf16 mma flash attention, block-diagonal mask ===============
// 4 warps; warp w owns query rows [16w,16w+16). KT=128 (fewer, fatter
// iterations); cp.async double-buffered K/V; V^T via ldmatrix.trans.
// Dynamic smem (~64 KB).
#define QT 64
#define KT 128
#define QSTW 20   // Qs/Ks/Vs word stride (32 bf16 = 16 words + 4 pad)
#define PSTW 68   // Pp word stride (128 keys = 64 bf16x2 words + 4 pad)

// smem layout (words)
#define FA_QS 0
#define FA_KS (FA_QS + QT * QSTW)                 // [2][KT*QSTW]
#define FA_VS (FA_KS + 2 * KT * QSTW)
#define FA_PP (FA_VS + 2 * KT * QSTW)             // [QT*PSTW]
#define FA_QB (FA_PP + QT * PSTW)                 // [QT] int
#define FA_KB (FA_QB + QT)                        // [2][KT] int
#define FA_WORDS (FA_KB + 2 * KT)                 // 16192 words = 64768 B

__device__ __forceinline__ int lb_search(const int* __restrict__ a, int n, int v) {
    int lo = 0, hi = n;
    while (lo < hi) { int mid = (lo + hi) >> 1; if (a[mid] < v) lo = mid + 1; else hi = mid; }
    return lo;
}
__device__ __forceinline__ int ub_search(const int* __restrict__ a, int n, int v) {
    int lo = 0, hi = n;
    while (lo < hi) { int mid = (lo + hi) >> 1; if (a[mid] <= v) lo = mid + 1; else hi = mid; }
    return lo;
}

__global__ void flash_attn_kernel(const __nv_bfloat16* __restrict__ qkv,
                                  const int* __restrict__ bidx,
                                  __nv_bfloat16* __restrict__ attn_out) {
    extern __shared__ uint32_t fsm[];
    uint32_t* Qs = fsm + FA_QS;
    uint32_t* KsB = fsm + FA_KS;
    uint32_t* VsB = fsm + FA_VS;
    uint32_t* Pp = fsm + FA_PP;
    int* qb = (int*)(fsm + FA_QB);
    int* kbB = (int*)(fsm + FA_KB);

    const int h = blockIdx.y;
    const int q0 = blockIdx.x * QT;
    const int t = threadIdx.x;            // 128 threads
    const int wid = t >> 5;
    const int lane = t & 31;
    const int g = lane >> 2;
    const int tq = lane & 3;
    const int qoff = h * HD;
    const int koff = D_MODEL + h * HD;
    const int voff = 2 * D_MODEL + h * HD;

    // zero K/V buffers once (tail keys stay finite -> P=0 kills them)
    for (int i = t; i < 2 * KT * QSTW; i += 128) {
        KsB[i] = 0;
        VsB[i] = 0;
    }
    // load Q tile: 64 rows x 4 uint4-chunks (8 bf16 each)
#pragma unroll
    for (int i = 0; i < 2; i++) {
        int fi = t + i * 128;
        int row = fi >> 2, c = fi & 3;
        *(uint4*)&Qs[row * QSTW + c * 4] =
            *(const uint4*)&qkv[(size_t)(q0 + row) * QKV_W + qoff + c * 8];
    }
    if (t < QT) qb[t] = bidx[q0 + t];
    __syncthreads();   // zero-fill + Q visible before cp.async lands on top

    const int myb0 = qb[wid * 16 + g];
    const int myb1 = qb[wid * 16 + g + 8];
    const int seg_s = lb_search(bidx, N_TOK, qb[0]);
    const int seg_e = ub_search(bidx, N_TOK, qb[QT - 1]);
    const int T = (seg_e - seg_s + KT - 1) / KT;

    auto issue_tile = [&](int k0, int buf) {
        const int kt = min(KT, seg_e - k0);
        uint32_t* Ks = KsB + buf * KT * QSTW;
        uint32_t* Vs = VsB + buf * KT * QSTW;
        int* kb = kbB + buf * KT;
        // 128 rows x 4 chunks of 16B each for K and V: 512 chunks,
        // each thread issues 4 K-chunks + 4 V-chunks.
#pragma unroll
        for (int i = 0; i < 4; i++) {
            int fi = t + i * 128;
            int kk = fi >> 2, c = fi & 3;
            if (kk < kt) {
                size_t base = (size_t)(k0 + kk) * QKV_W;
                cp_async16((uint32_t)__cvta_generic_to_shared(&Ks[kk * QSTW + c * 4]),
                           qkv + base + koff + c * 8);
                cp_async16((uint32_t)__cvta_generic_to_shared(&Vs[kk * QSTW + c * 4]),
                           qkv + base + voff + c * 8);
            }
        }
        if (t < KT) kb[t] = (t < kt) ? bidx[k0 + t] : -1;
        cp_commit();
    };

    issue_tile(seg_s, 0);

    // Q fragments (2 k16 steps)
    uint32_t qf[2][4];
#pragma unroll
    for (int ks = 0; ks < 2; ks++) {
        int base = (wid * 16 + g) * QSTW + ks * 8;
        int base8 = (wid * 16 + g + 8) * QSTW + ks * 8;
        qf[ks][0] = Qs[base + tq];
        qf[ks][1] = Qs[base8 + tq];
        qf[ks][2] = Qs[base + tq + 4];
        qf[ks][3] = Qs[base8 + tq + 4];
    }

    const float scale = 0.1767766952966369f; // 1/sqrt(32)
    float m0 = 0.f, m1 = 0.f, l0 = 0.f, l1 = 0.f;  // max init 0 (valid upper bound)
    float oacc[4][4];
#pragma unroll
    for (int nt = 0; nt < 4; nt++)
#pragma unroll
        for (int c = 0; c < 4; c++) oacc[nt][c] = 0.f;

    for (int i = 0; i < T; i++) {
        const int cur = i & 1;
        if (i > 0) __syncthreads();        // all warps done with buffer (i+1)&1
        if (i + 1 < T) issue_tile(seg_s + (i + 1) * KT, cur ^ 1);
        if (i + 1 < T) cp_wait<1>(); else cp_wait<0>();
        __syncthreads();                   // tile i data + kb visible

        const uint32_t* Kc = KsB + cur * KT * QSTW;
        const int* kbc = kbB + cur * KT;
        const uint32_t vsbase = (uint32_t)__cvta_generic_to_shared(&VsB[cur * KT * QSTW]);

        // ---- S = Q K^T: 2 k16 steps x 16 n-tiles ----
        float sacc[16][4];
#pragma unroll
        for (int nt = 0; nt < 16; nt++)
#pragma unroll
            for (int c = 0; c < 4; c++) sacc[nt][c] = 0.f;
#pragma unroll
        for (int ks = 0; ks < 2; ks++) {
            const int kw = ks * 8;
#pragma unroll
            for (int nt = 0; nt < 16; nt++) {
                int kr = (nt * 8 + g) * QSTW + kw;
                mma_bf16(sacc[nt][0], sacc[nt][1], sacc[nt][2], sacc[nt][3],
                         qf[ks][0], qf[ks][1], qf[ks][2], qf[ks][3],
                         Kc[kr + tq], Kc[kr + tq + 4]);
            }
        }

        // ---- mask + row max ----
        float rmax0 = -1e30f, rmax1 = -1e30f;
#pragma unroll
        for (int nt = 0; nt < 16; nt++) {
            int c0 = nt * 8 + 2 * tq;
            int kb0 = kbc[c0], kb1 = kbc[c0 + 1];
            float s0 = (kb0 == myb0) ? sacc[nt][0] * scale : -1e30f;
            float s1 = (kb1 == myb0) ? sacc[nt][1] * scale : -1e30f;
            float s2 = (kb0 == myb1) ? sacc[nt][2] * scale : -1e30f;
            float s3 = (kb1 == myb1) ? sacc[nt][3] * scale : -1e30f;
            sacc[nt][0] = s0; sacc[nt][1] = s1; sacc[nt][2] = s2; sacc[nt][3] = s3;
            rmax0 = fmaxf(rmax0, fmaxf(s0, s1));
            rmax1 = fmaxf(rmax1, fmaxf(s2, s3));
        }
        rmax0 = fmaxf(rmax0, __shfl_xor_sync(0xffffffffu, rmax0, 1));
        rmax0 = fmaxf(rmax0, __shfl_xor_sync(0xffffffffu, rmax0, 2));
        rmax1 = fmaxf(rmax1, __shfl_xor_sync(0xffffffffu, rmax1, 1));
        rmax1 = fmaxf(rmax1, __shfl_xor_sync(0xffffffffu, rmax1, 2));
        const float mn0 = fmaxf(m0, rmax0);
        const float mn1 = fmaxf(m1, rmax1);
        const float al0 = __expf(m0 - mn0);
        const float al1 = __expf(m1 - mn1);
        m0 = mn0; m1 = mn1;

        // ---- exp, pack P to bf16 pairs, update l ----
        float ls0 = 0.f, ls1 = 0.f;
        const int pr0 = (wid * 16 + g) * PSTW;
        const int pr1 = (wid * 16 + g + 8) * PSTW;
#pragma unroll
        for (int nt = 0; nt < 16; nt++) {
            float p0 = __expf(sacc[nt][0] - mn0);
            float p1 = __expf(sacc[nt][1] - mn0);
            float p2 = __expf(sacc[nt][2] - mn1);
            float p3 = __expf(sacc[nt][3] - mn1);
            ls0 += p0 + p1;
            ls1 += p2 + p3;
            Pp[pr0 + nt * 4 + tq] = pack_bf16x2(p0, p1);
            Pp[pr1 + nt * 4 + tq] = pack_bf16x2(p2, p3);
        }
        ls0 += __shfl_xor_sync(0xffffffffu, ls0, 1);
        ls0 += __shfl_xor_sync(0xffffffffu, ls0, 2);
        ls1 += __shfl_xor_sync(0xffffffffu, ls1, 1);
        ls1 += __shfl_xor_sync(0xffffffffu, ls1, 2);
        l0 = l0 * al0 + ls0;
        l1 = l1 * al1 + ls1;
#pragma unroll
        for (int nt = 0; nt < 4; nt++) {
            oacc[nt][0] *= al0; oacc[nt][1] *= al0;
            oacc[nt][2] *= al1; oacc[nt][3] *= al1;
        }
        __syncwarp();  // warp-local P rows visible

        // ---- O += P V: ldmatrix.trans V fragments; 4 key-halves x 2 k16 ----
#pragma unroll
        for (int half = 0; half < 4; half++) {
            const int key0 = half * 32;
            uint32_t vb[4][4];  // [d-block nt][key octet 0..3 within half]
#pragma unroll
            for (int nt = 0; nt < 4; nt++) {
                uint32_t addr = vsbase + ((key0 + lane) * QSTW + nt * 4) * 4;
                ldsm_x4_trans(vb[nt][0], vb[nt][1], vb[nt][2], vb[nt][3], addr);
            }
#pragma unroll
            for (int ks = 0; ks < 2; ks++) {
                const int kw = (half * 2 + ks) * 8;
                uint32_t a0 = Pp[pr0 + kw + tq];
                uint32_t a1 = Pp[pr1 + kw + tq];
                uint32_t a2 = Pp[pr0 + kw + tq + 4];
                uint32_t a3 = Pp[pr1 + kw + tq + 4];
#pragma unroll
                for (int nt = 0; nt < 4; nt++)
                    mma_bf16(oacc[nt][0], oacc[nt][1], oacc[nt][2], oacc[nt][3],
                             a0, a1, a2, a3, vb[nt][ks * 2], vb[nt][ks * 2 + 1]);
            }
        }
    }

    const float i0 = 1.f / l0;
    const float i1 = 1.f / l1;
    const int r0 = q0 + wid * 16 + g;
    const int r1 = r0 + 8;
#pragma unroll
    for (int nt = 0; nt < 4; nt++) {
        int col = h * HD + nt * 8 + 2 * tq;
        *(uint32_t*)&attn_out[(size_t)r0 * D_MODEL + col] = pack_bf16x2(oacc[nt][0] * i0, oacc[nt][1] * i0);
        *(uint32_t*)&attn_out[(size_t)r1 * D_MODEL + col] = pack_bf16x2(oacc[nt][2] * i1, oacc[nt][3] * i1);
    }
}

// ---------------- launch ----------------------------------------------------
extern "C" void kernel_launch(void* const* d_in, const int* in_sizes, int n_in,
                              void* d_out, int out_size) {
    const float* slots    = (const float*)d_in[0];
    const int*   batch_ix = (const int*)d_in[1];
    const float* w_in     = (const float*)d_in[2];
    const float* b_in     = (const float*)d_in[3];
    const float* w_out    = (const float*)d_in[4];
    const float* b_out    = (const float*)d_in[5];
    const float* ln_gamma = (const float*)d_in[6];
    const float* ln_beta  = (const float*)d_in[7];
    float* out = (float*)d_out;

    __nv_bfloat16* qkv_bf;   cudaGetSymbolAddress((void**)&qkv_bf,   g_qkv_bf);
    __nv_bfloat16* attn_bf;  cudaGetSymbolAddress((void**)&attn_bf,  g_attn_bf);
    __nv_bfloat16* slots_bf; cudaGetSymbolAddress((void**)&slots_bf, g_slots_bf);
    __nv_bfloat16* win_bf;   cudaGetSymbolAddress((void**)&win_bf,   g_win_bf);
    __nv_bfloat16* wout_bf;  cudaGetSymbolAddress((void**)&wout_bf,  g_wout_bf);

    // 0) convert inputs to bf16 (slots, w_in, w_out)
    {
        const int n0 = N_TOK * D_MODEL, n1 = QKV_W * D_MODEL, n2 = D_MODEL * D_MODEL;
        const int total4 = (n0 + n1 + n2) / 4;
        cvt_bf16_kernel<<<(total4 + 255) / 256, 256>>>(slots, slots_bf, n0,
                                                       w_in, win_bf, n1,
                                                       w_out, wout_bf, n2);
    }
    // 1) QKV projection (bf16 in/out, BK=64 depth-2): qkv = slots @ w_in^T + b_in
    {
        dim3 grid(QKV_W / GBN, N_TOK / GBM);
        gemm_bf16_kernel<<<grid, 256>>>(slots_bf, win_bf, b_in, qkv_bf,
                                        N_TOK, QKV_W, D_MODEL);
    }
    // 2) block-diagonal flash attention (bf16 mma, KT=128, dynamic smem)
    {
        const int fa_smem = FA_WORDS * (int)sizeof(uint32_t);  // ~64.8 KB
        cudaFuncSetAttribute(flash_attn_kernel,
                             cudaFuncAttributeMaxDynamicSharedMemorySize, fa_smem);
        dim3 grid(N_TOK / QT, H_HEADS);
        flash_attn_kernel<<<grid, 128, fa_smem>>>(qkv_bf, batch_ix, attn_bf);
    }
    // 3) fused out-projection + bias + residual + LayerNorm (BK=64, 512 t)
    {
        const int smem_bytes = G2WORDS * (int)sizeof(uint32_t);  // ~116 KB
        cudaFuncSetAttribute(gemm2_ln_kernel,
                             cudaFuncAttributeMaxDynamicSharedMemorySize, smem_bytes);
        gemm2_ln_kernel<<<N_TOK / G2BM, 512, smem_bytes>>>(attn_bf, wout_bf, b_out, slots,
                                                           ln_gamma, ln_beta, out);
    }
}

// round 17
// speedup vs baseline: 1.0401x; 1.0401x over previous
#include <cuda_runtime.h>
#include <cuda_bf16.h>
#include <math.h>
#include <stdint.h>

#define N_TOK 4096
#define D_MODEL 256
#define H_HEADS 8
#define HD 32
#define QKV_W 768

// ---------------- scratch (device globals; no allocation allowed) ----------
__device__ __nv_bfloat16 g_qkv_bf[N_TOK * QKV_W];      // bf16 q|k|v
__device__ __nv_bfloat16 g_attn_bf[N_TOK * D_MODEL];   // attention out (bf16)
__device__ __nv_bfloat16 g_slots_bf[N_TOK * D_MODEL];
__device__ __nv_bfloat16 g_win_bf[QKV_W * D_MODEL];
__device__ __nv_bfloat16 g_wout_bf[D_MODEL * D_MODEL];

// =================== mma / cp.async / ldmatrix helpers =====================
__device__ __forceinline__ void mma_bf16(float& d0, float& d1, float& d2, float& d3,
                                         uint32_t a0, uint32_t a1, uint32_t a2, uint32_t a3,
                                         uint32_t b0, uint32_t b1) {
    asm volatile("mma.sync.aligned.m16n8k16.row.col.f32.bf16.bf16.f32 "
                 "{%0,%1,%2,%3}, {%4,%5,%6,%7}, {%8,%9}, {%0,%1,%2,%3};"
                 : "+f"(d0), "+f"(d1), "+f"(d2), "+f"(d3)
                 : "r"(a0), "r"(a1), "r"(a2), "r"(a3), "r"(b0), "r"(b1));
}

__device__ __forceinline__ void cp_async16(uint32_t dst, const void* src) {
    asm volatile("cp.async.cg.shared.global [%0], [%1], 16;" :: "r"(dst), "l"(src));
}
__device__ __forceinline__ void cp_commit() {
    asm volatile("cp.async.commit_group;");
}
template <int Nwait>
__device__ __forceinline__ void cp_wait() {
    asm volatile("cp.async.wait_group %0;" :: "n"(Nwait));
}

// transposed 8x8 b16 x4 loads (for V^T fragments)
__device__ __forceinline__ void ldsm_x4_trans(uint32_t& r0, uint32_t& r1,
                                              uint32_t& r2, uint32_t& r3, uint32_t addr) {
    asm volatile("ldmatrix.sync.aligned.m8n8.x4.trans.shared.b16 {%0,%1,%2,%3}, [%4];"
                 : "=r"(r0), "=r"(r1), "=r"(r2), "=r"(r3) : "r"(addr));
}

// pack two fp32 into one bf16x2 register (lo -> low half, hi -> high half)
__device__ __forceinline__ uint32_t pack_bf16x2(float lo, float hi) {
    uint32_t r;
    asm("cvt.rn.bf16x2.f32 %0, %1, %2;" : "=r"(r) : "f"(hi), "f"(lo));
    return r;
}

// =================== fp32 -> bf16 conversion (3 arrays, one launch) ========
__global__ void cvt_bf16_kernel(const float* __restrict__ s0, __nv_bfloat16* __restrict__ d0, int n0,
                                const float* __restrict__ s1, __nv_bfloat16* __restrict__ d1, int n1,
                                const float* __restrict__ s2, __nv_bfloat16* __restrict__ d2, int n2) {
    int i = blockIdx.x * blockDim.x + threadIdx.x;  // one float4 per thread
    const float* s;
    __nv_bfloat16* d;
    int off;
    int q0 = n0 >> 2, q1 = q0 + (n1 >> 2), q2 = q1 + (n2 >> 2);
    if (i >= q2) return;
    if (i < q0) { s = s0; d = d0; off = i * 4; }
    else if (i < q1) { s = s1; d = d1; off = (i - q0) * 4; }
    else { s = s2; d = d2; off = (i - q1) * 4; }
    float4 v = *(const float4*)&s[off];
    *(uint32_t*)&d[off] = pack_bf16x2(v.x, v.y);
    *(uint32_t*)&d[off + 2] = pack_bf16x2(v.z, v.w);
}

// ===== bf16 GEMM1: C[M,N] = A[M,K] @ B[N,K]^T + bias, bf16 output ==========
// Block tile 128x64, 8 warps (4x2), warp tile 32x32. BK=64 -> 4 stages,
// depth-2 pipeline, stride-36 smem (conflict-free frags), ~55 KB smem.
#define GBM 128
#define GBN 64
#define GBK 64
#define G1STW 36

__global__ void gemm_bf16_kernel(const __nv_bfloat16* __restrict__ A,
                                 const __nv_bfloat16* __restrict__ B,
                                 const float* __restrict__ bias,
                                 __nv_bfloat16* __restrict__ C,
                                 int M, int N, int K) {
    __shared__ uint32_t As[2 * GBM * G1STW];
    __shared__ uint32_t Bs[2 * GBN * G1STW];

    const int t = threadIdx.x;            // 256 threads
    const int wid = t >> 5;
    const int lane = t & 31;
    const int g = lane >> 2;
    const int tq = lane & 3;
    const int wm = (wid & 3) * 32;
    const int wn = (wid >> 2) * 32;
    const int m0 = blockIdx.y * GBM;
    const int n0 = blockIdx.x * GBN;

    float acc[2][4][4];
#pragma unroll
    for (int mi = 0; mi < 2; mi++)
#pragma unroll
        for (int ni = 0; ni < 4; ni++)
#pragma unroll
            for (int c = 0; c < 4; c++) acc[mi][ni][c] = 0.f;

    const int T = K / GBK;                // 4 stages

    auto issue = [&](int kt, int buf) {
        const __nv_bfloat16* Ab = A + (size_t)m0 * K + kt * GBK;
#pragma unroll
        for (int i = 0; i < 4; i++) {     // A: 128 rows x 8 chunks = 1024
            int fi = t + i * 256;
            int row = fi >> 3, c16 = fi & 7;
            cp_async16((uint32_t)__cvta_generic_to_shared(&As[(buf * GBM + row) * G1STW + c16 * 4]),
                       Ab + (size_t)row * K + c16 * 8);
        }
        const __nv_bfloat16* Bb = B + (size_t)n0 * K + kt * GBK;
#pragma unroll
        for (int i = 0; i < 2; i++) {     // B: 64 rows x 8 chunks = 512
            int fi = t + i * 256;
            int row = fi >> 3, c16 = fi & 7;
            cp_async16((uint32_t)__cvta_generic_to_shared(&Bs[(buf * GBN + row) * G1STW + c16 * 4]),
                       Bb + (size_t)row * K + c16 * 8);
        }
        cp_commit();
    };

    issue(0, 0);
    if (T > 1) issue(1, 1);

    for (int i = 0; i < T; i++) {
        if (i + 1 < T) cp_wait<1>(); else cp_wait<0>();
        __syncthreads();

        const uint32_t* Ab = As + (i & 1) * GBM * G1STW;
        const uint32_t* Bb = Bs + (i & 1) * GBN * G1STW;
#pragma unroll
        for (int ks = 0; ks < 4; ks++) {  // four k16 steps per BK=64
            const int kw = ks * 8;
            uint32_t a[2][4];
#pragma unroll
            for (int mi = 0; mi < 2; mi++) {
                int r0 = wm + mi * 16 + g;
                a[mi][0] = Ab[r0 * G1STW + kw + tq];
                a[mi][1] = Ab[(r0 + 8) * G1STW + kw + tq];
                a[mi][2] = Ab[r0 * G1STW + kw + tq + 4];
                a[mi][3] = Ab[(r0 + 8) * G1STW + kw + tq + 4];
            }
#pragma unroll
            for (int ni = 0; ni < 4; ni++) {
                int bc = wn + ni * 8 + g;
                uint32_t b0 = Bb[bc * G1STW + kw + tq];
                uint32_t b1 = Bb[bc * G1STW + kw + tq + 4];
#pragma unroll
                for (int mi = 0; mi < 2; mi++)
                    mma_bf16(acc[mi][ni][0], acc[mi][ni][1], acc[mi][ni][2], acc[mi][ni][3],
                             a[mi][0], a[mi][1], a[mi][2], a[mi][3], b0, b1);
            }
        }
        __syncthreads();
        if (i + 2 < T) issue(i + 2, i & 1);
    }

#pragma unroll
    for (int mi = 0; mi < 2; mi++) {
#pragma unroll
        for (int ni = 0; ni < 4; ni++) {
            int col = n0 + wn + ni * 8 + 2 * tq;
            int r0 = m0 + wm + mi * 16 + g;
            int r1 = r0 + 8;
            float bx = bias[col], by = bias[col + 1];
            *(uint32_t*)&C[(size_t)r0 * N + col] = pack_bf16x2(acc[mi][ni][0] + bx, acc[mi][ni][1] + by);
            *(uint32_t*)&C[(size_t)r1 * N + col] = pack_bf16x2(acc[mi][ni][2] + bx, acc[mi][ni][3] + by);
        }
    }
}

// ====== fused GEMM2 + bias + residual + LayerNorm (R13/R15 config) =========
#define G2BM 32
#define G2BN 256
#define G2BK 64
#define G2STW 36                                      // 32 data words + 4 pad
#define G2AB (2 * G2BM * G2STW + 2 * G2BN * G2STW)    // 20736 words
#define G2RES G2AB                                     // resid: 8192 words
#define G2PAR (G2AB + G2BM * 256)                      // bias|gamma|beta: 768
#define G2WORDS (G2PAR + 768)                          // 29696 words (~116 KB)

__global__ void gemm2_ln_kernel(const __nv_bfloat16* __restrict__ A,
                                const __nv_bfloat16* __restrict__ B,
                                const float* __restrict__ bias,
                                const float* __restrict__ resid,
                                const float* __restrict__ gamma,
                                const float* __restrict__ beta,
                                float* __restrict__ out) {
    extern __shared__ uint32_t sm[];
    uint32_t* As = sm;                      // [2][G2BM][G2STW]
    uint32_t* Bs = sm + 2 * G2BM * G2STW;   // [2][G2BN][G2STW]
    float* Rs = (float*)(sm + G2RES);       // [32][256] residual
    float* Pv = (float*)(sm + G2PAR);       // bias[256] gamma[256] beta[256]
    float* Cs = (float*)sm;                 // epilogue alias, stride 264

    const int t = threadIdx.x;              // 512 threads
    const int wid = t >> 5;                 // 0..15
    const int lane = t & 31;
    const int g = lane >> 2;
    const int tq = lane & 3;
    const int wm = (wid & 1) * 16;
    const int wn = (wid >> 1) * 32;
    const int m0 = blockIdx.x * G2BM;
    const int K = 256, T = 4;               // 4 stages of BK=64

    float acc[4][4];
#pragma unroll
    for (int ni = 0; ni < 4; ni++)
#pragma unroll
        for (int c = 0; c < 4; c++) acc[ni][c] = 0.f;

    auto issue = [&](int kt, int buf) {
        if (t < 256) {                      // A: 32 rows x 8 chunks
            int row = t >> 3, c16 = t & 7;
            cp_async16((uint32_t)__cvta_generic_to_shared(&As[(buf * G2BM + row) * G2STW + c16 * 4]),
                       A + (size_t)(m0 + row) * K + kt * G2BK + c16 * 8);
        }
#pragma unroll
        for (int i = 0; i < 4; i++) {       // B: 256 rows x 8 chunks = 2048
            int fi = t + i * 512;
            int row = fi >> 3, c16 = fi & 7;
            cp_async16((uint32_t)__cvta_generic_to_shared(&Bs[(buf * G2BN + row) * G2STW + c16 * 4]),
                       B + (size_t)row * K + kt * G2BK + c16 * 8);
        }
        // resid rows [kt*8, kt*8+8): 8 rows x 64 chunks = 512 (all threads)
        {
            int rr = kt * 8 + (t >> 6);
            int c4 = t & 63;
            cp_async16((uint32_t)__cvta_generic_to_shared(&Rs[rr * 256 + c4 * 4]),
                       resid + (size_t)(m0 + rr) * 256 + c4 * 4);
        }
        if (kt == 0) {                      // params: 192 chunks
            if (t < 64)
                cp_async16((uint32_t)__cvta_generic_to_shared(&Pv[t * 4]), bias + t * 4);
            else if (t < 128)
                cp_async16((uint32_t)__cvta_generic_to_shared(&Pv[256 + (t - 64) * 4]), gamma + (t - 64) * 4);
            else if (t < 192)
                cp_async16((uint32_t)__cvta_generic_to_shared(&Pv[512 + (t - 128) * 4]), beta + (t - 128) * 4);
        }
        cp_commit();
    };

    issue(0, 0);
    issue(1, 1);

    for (int i = 0; i < T; i++) {
        if (i + 1 < T) cp_wait<1>(); else cp_wait<0>();
        __syncthreads();

        const uint32_t* Ab = As + (i & 1) * G2BM * G2STW;
        const uint32_t* Bb = Bs + (i & 1) * G2BN * G2STW;
#pragma unroll
        for (int ks = 0; ks < 4; ks++) {
            const int kw = ks * 8;
            uint32_t a0 = Ab[(wm + g) * G2STW + kw + tq];
            uint32_t a1 = Ab[(wm + g + 8) * G2STW + kw + tq];
            uint32_t a2 = Ab[(wm + g) * G2STW + kw + tq + 4];
            uint32_t a3 = Ab[(wm + g + 8) * G2STW + kw + tq + 4];
#pragma unroll
            for (int ni = 0; ni < 4; ni++) {
                int bc = wn + ni * 8 + g;
                uint32_t b0 = Bb[bc * G2STW + kw + tq];
                uint32_t b1 = Bb[bc * G2STW + kw + tq + 4];
                mma_bf16(acc[ni][0], acc[ni][1], acc[ni][2], acc[ni][3],
                         a0, a1, a2, a3, b0, b1);
            }
        }
        __syncthreads();
        if (i + 2 < T) issue(i + 2, i & 1);
    }

    // stage acc + bias into smem (full 256-wide rows; aliases AB buffers)
#pragma unroll
    for (int ni = 0; ni < 4; ni++) {
        int col = wn + ni * 8 + 2 * tq;
        float bx = Pv[col], by = Pv[col + 1];
        *(float2*)&Cs[(wm + g) * 264 + col] = make_float2(acc[ni][0] + bx, acc[ni][1] + by);
        *(float2*)&Cs[(wm + g + 8) * 264 + col] = make_float2(acc[ni][2] + bx, acc[ni][3] + by);
    }
    __syncthreads();

    // LayerNorm: warp w handles rows 2w, 2w+1; all operands in smem
#pragma unroll
    for (int rr = wid * 2; rr < wid * 2 + 2; rr++) {
        float v[8], s = 0.f;
#pragma unroll
        for (int k = 0; k < 8; k++) {
            int c = lane + 32 * k;
            v[k] = Cs[rr * 264 + c] + Rs[rr * 256 + c];
            s += v[k];
        }
#pragma unroll
        for (int o = 16; o > 0; o >>= 1) s += __shfl_xor_sync(0xffffffffu, s, o);
        const float mean = s * (1.f / 256.f);
        float sq = 0.f;
#pragma unroll
        for (int k = 0; k < 8; k++) { float d = v[k] - mean; sq += d * d; }
#pragma unroll
        for (int o = 16; o > 0; o >>= 1) sq += __shfl_xor_sync(0xffffffffu, sq, o);
        const float rsig = rsqrtf(sq * (1.f / 256.f) + 1e-5f);
#pragma unroll
        for (int k = 0; k < 8; k++) {
            int c = lane + 32 * k;
            out[(size_t)(m0 + rr) * 256 + c] = (v[k] - mean) * rsig * Pv[256 + c] + Pv[512 + c];
        }
    }
}

// ============== bf16 mma flash attention, block-diagonal mask ===============
// 4 warps; warp w owns query rows [16w,16w+16). KT=64, cp.async double-
// buffered K/V; V^T via ldmatrix.trans. P stays in registers: the S
// C-fragment layout equals the PV A-fragment layout (no smem round-trip).
#define QT 64
#define KT 64
#define QSTW 20   // Qs/Ks/Vs word stride (32 bf16 = 16 words + 4 pad)

__device__ __forceinline__ int lb_search(const int* __restrict__ a, int n, int v) {
    int lo = 0, hi = n;
    while (lo < hi) { int mid = (lo + hi) >> 1; if (a[mid] < v) lo = mid + 1; else hi = mid; }
    return lo;
}
__device__ __forceinline__ int ub_search(const int* __restrict__ a, int n, int v) {
    int lo = 0, hi = n;
    while (lo < hi) { int mid = (lo + hi) >> 1; if (a[mid] <= v) lo = mid + 1; else hi = mid; }
    return lo;
}

__global__ void flash_attn_kernel(const __nv_bfloat16* __restrict__ qkv,
                                  const int* __restrict__ bidx,
                                  __nv_bfloat16* __restrict__ attn_out) {
    __shared__ uint32_t Qs[QT * QSTW];
    __shared__ uint32_t Ks[2][KT * QSTW];
    __shared__ uint32_t Vs[2][KT * QSTW];   // row-major [key][d]
    __shared__ int qb[QT];
    __shared__ int kb[2][KT];

    const int h = blockIdx.y;
    const int q0 = blockIdx.x * QT;
    const int t = threadIdx.x;            // 128 threads
    const int wid = t >> 5;
    const int lane = t & 31;
    const int g = lane >> 2;
    const int tq = lane & 3;
    const int qoff = h * HD;
    const int koff = D_MODEL + h * HD;
    const int voff = 2 * D_MODEL + h * HD;

    // zero K/V buffers once (so tail keys are always finite -> P=0 kills them)
#pragma unroll
    for (int i = t; i < 2 * KT * QSTW; i += 128) {
        ((uint32_t*)Ks)[i] = 0;
        ((uint32_t*)Vs)[i] = 0;
    }
    // load Q tile: 64 rows x 4 uint4-chunks (8 bf16 each)
#pragma unroll
    for (int i = 0; i < 2; i++) {
        int fi = t + i * 128;
        int row = fi >> 2, c = fi & 3;
        *(uint4*)&Qs[row * QSTW + c * 4] =
            *(const uint4*)&qkv[(size_t)(q0 + row) * QKV_W + qoff + c * 8];
    }
    if (t < QT) qb[t] = bidx[q0 + t];
    __syncthreads();   // zero-fill + Q visible before cp.async lands on top

    const int myb0 = qb[wid * 16 + g];
    const int myb1 = qb[wid * 16 + g + 8];
    const int seg_s = lb_search(bidx, N_TOK, qb[0]);
    const int seg_e = ub_search(bidx, N_TOK, qb[QT - 1]);
    const int T = (seg_e - seg_s + KT - 1) / KT;

    auto issue_tile = [&](int k0, int buf) {
        const int kt = min(KT, seg_e - k0);
        // 64 rows x 4 chunks of 16B each for K and V: fi covers 256 chunks,
        // each thread issues 2 K-chunks + 2 V-chunks (full 64-byte rows).
#pragma unroll
        for (int i = 0; i < 2; i++) {
            int fi = t + i * 128;
            int kk = fi >> 2, c = fi & 3;
            if (kk < kt) {
                size_t base = (size_t)(k0 + kk) * QKV_W;
                cp_async16((uint32_t)__cvta_generic_to_shared(&Ks[buf][kk * QSTW + c * 4]),
                           qkv + base + koff + c * 8);
                cp_async16((uint32_t)__cvta_generic_to_shared(&Vs[buf][kk * QSTW + c * 4]),
                           qkv + base + voff + c * 8);
            }
        }
        if (t < KT) kb[buf][t] = (t < kt) ? bidx[k0 + t] : -1;
        cp_commit();
    };

    issue_tile(seg_s, 0);

    // Q fragments (2 k16 steps)
    uint32_t qf[2][4];
#pragma unroll
    for (int ks = 0; ks < 2; ks++) {
        int base = (wid * 16 + g) * QSTW + ks * 8;
        int base8 = (wid * 16 + g + 8) * QSTW + ks * 8;
        qf[ks][0] = Qs[base + tq];
        qf[ks][1] = Qs[base8 + tq];
        qf[ks][2] = Qs[base + tq + 4];
        qf[ks][3] = Qs[base8 + tq + 4];
    }

    const float scale = 0.1767766952966369f; // 1/sqrt(32)
    float m0 = 0.f, m1 = 0.f, l0 = 0.f, l1 = 0.f;  // max init 0 (valid upper bound)
    float oacc[4][4];
#pragma unroll
    for (int nt = 0; nt < 4; nt++)
#pragma unroll
        for (int c = 0; c < 4; c++) oacc[nt][c] = 0.f;

    for (int i = 0; i < T; i++) {
        const int cur = i & 1;
        if (i > 0) __syncthreads();        // all warps done with buffer (i+1)&1
        if (i + 1 < T) issue_tile(seg_s + (i + 1) * KT, cur ^ 1);
        if (i + 1 < T) cp_wait<1>(); else cp_wait<0>();
        __syncthreads();                   // tile i data + kb visible

        const uint32_t* Kc = Ks[cur];
        const int* kbc = kb[cur];
        const uint32_t vsbase = (uint32_t)__cvta_generic_to_shared(&Vs[cur][0]);

        // ---- S = Q K^T: 2 k16 steps x 8 n-tiles ----
        float sacc[8][4];
#pragma unroll
        for (int nt = 0; nt < 8; nt++)
#pragma unroll
            for (int c = 0; c < 4; c++) sacc[nt][c] = 0.f;
#pragma unroll
        for (int ks = 0; ks < 2; ks++) {
            const int kw = ks * 8;
#pragma unroll
            for (int nt = 0; nt < 8; nt++) {
                int kr = (nt * 8 + g) * QSTW + kw;
                mma_bf16(sacc[nt][0], sacc[nt][1], sacc[nt][2], sacc[nt][3],
                         qf[ks][0], qf[ks][1], qf[ks][2], qf[ks][3],
                         Kc[kr + tq], Kc[kr + tq + 4]);
            }
        }

        // ---- mask + row max ----
        float rmax0 = -1e30f, rmax1 = -1e30f;
#pragma unroll
        for (int nt = 0; nt < 8; nt++) {
            int c0 = nt * 8 + 2 * tq;
            int kb0 = kbc[c0], kb1 = kbc[c0 + 1];
            float s0 = (kb0 == myb0) ? sacc[nt][0] * scale : -1e30f;
            float s1 = (kb1 == myb0) ? sacc[nt][1] * scale : -1e30f;
            float s2 = (kb0 == myb1) ? sacc[nt][2] * scale : -1e30f;
            float s3 = (kb1 == myb1) ? sacc[nt][3] * scale : -1e30f;
            sacc[nt][0] = s0; sacc[nt][1] = s1; sacc[nt][2] = s2; sacc[nt][3] = s3;
            rmax0 = fmaxf(rmax0, fmaxf(s0, s1));
            rmax1 = fmaxf(rmax1, fmaxf(s2, s3));
        }
        rmax0 = fmaxf(rmax0, __shfl_xor_sync(0xffffffffu, rmax0, 1));
        rmax0 = fmaxf(rmax0, __shfl_xor_sync(0xffffffffu, rmax0, 2));
        rmax1 = fmaxf(rmax1, __shfl_xor_sync(0xffffffffu, rmax1, 1));
        rmax1 = fmaxf(rmax1, __shfl_xor_sync(0xffffffffu, rmax1, 2));
        const float mn0 = fmaxf(m0, rmax0);
        const float mn1 = fmaxf(m1, rmax1);
        const float al0 = __expf(m0 - mn0);
        const float al1 = __expf(m1 - mn1);
        m0 = mn0; m1 = mn1;

        // ---- exp, pack P directly into A-fragment registers, update l ----
        // S C-frag (rows g/g+8, cols 2tq,2tq+1 of n-tile nt) == PV A-frag:
        // k16-step kk uses pa[2kk] (keys 16kk..+7) and pa[2kk+1] (keys +8..15):
        //   a0 = pack(p[2kk][0], p[2kk][1])   (row g)
        //   a1 = pack(p[2kk][2], p[2kk][3])   (row g+8)
        //   a2 = pack(p[2kk+1][0], p[2kk+1][1])
        //   a3 = pack(p[2kk+1][2], p[2kk+1][3])
        float ls0 = 0.f, ls1 = 0.f;
        uint32_t pa[8][2];
#pragma unroll
        for (int nt = 0; nt < 8; nt++) {
            float p0 = __expf(sacc[nt][0] - mn0);
            float p1 = __expf(sacc[nt][1] - mn0);
            float p2 = __expf(sacc[nt][2] - mn1);
            float p3 = __expf(sacc[nt][3] - mn1);
            ls0 += p0 + p1;
            ls1 += p2 + p3;
            pa[nt][0] = pack_bf16x2(p0, p1);
            pa[nt][1] = pack_bf16x2(p2, p3);
        }
        ls0 += __shfl_xor_sync(0xffffffffu, ls0, 1);
        ls0 += __shfl_xor_sync(0xffffffffu, ls0, 2);
        ls1 += __shfl_xor_sync(0xffffffffu, ls1, 1);
        ls1 += __shfl_xor_sync(0xffffffffu, ls1, 2);
        l0 = l0 * al0 + ls0;
        l1 = l1 * al1 + ls1;
#pragma unroll
        for (int nt = 0; nt < 4; nt++) {
            oacc[nt][0] *= al0; oacc[nt][1] *= al0;
            oacc[nt][2] *= al1; oacc[nt][3] *= al1;
        }

        // ---- O += P V: ldmatrix.trans V frags; 2 key-halves x 2 k16 ----
#pragma unroll
        for (int half = 0; half < 2; half++) {
            const int key0 = half * 32;
            uint32_t vb[4][4];  // [d-block nt][key octet 0..3 within half]
#pragma unroll
            for (int nt = 0; nt < 4; nt++) {
                uint32_t addr = vsbase + ((key0 + lane) * QSTW + nt * 4) * 4;
                ldsm_x4_trans(vb[nt][0], vb[nt][1], vb[nt][2], vb[nt][3], addr);
            }
#pragma unroll
            for (int ks = 0; ks < 2; ks++) {
                const int kk = half * 2 + ks;        // k16-step 0..3
                uint32_t a0 = pa[2 * kk][0];
                uint32_t a1 = pa[2 * kk][1];
                uint32_t a2 = pa[2 * kk + 1][0];
                uint32_t a3 = pa[2 * kk + 1][1];
#pragma unroll
                for (int nt = 0; nt < 4; nt++)
                    mma_bf16(oacc[nt][0], oacc[nt][1], oacc[nt][2], oacc[nt][3],
                             a0, a1, a2, a3, vb[nt][ks * 2], vb[nt][ks * 2 + 1]);
            }
        }
    }

    const float i0 = 1.f / l0;
    const float i1 = 1.f / l1;
    const int r0 = q0 + wid * 16 + g;
    const int r1 = r0 + 8;
#pragma unroll
    for (int nt = 0; nt < 4; nt++) {
        int col = h * HD + nt * 8 + 2 * tq;
        *(uint32_t*)&attn_out[(size_t)r0 * D_MODEL + col] = pack_bf16x2(oacc[nt][0] * i0, oacc[nt][1] * i0);
        *(uint32_t*)&attn_out[(size_t)r1 * D_MODEL + col] = pack_bf16x2(oacc[nt][2] * i1, oacc[nt][3] * i1);
    }
}

// ---------------- launch ----------------------------------------------------
extern "C" void kernel_launch(void* const* d_in, const int* in_sizes, int n_in,
                              void* d_out, int out_size) {
    const float* slots    = (const float*)d_in[0];
    const int*   batch_ix = (const int*)d_in[1];
    const float* w_in     = (const float*)d_in[2];
    const float* b_in     = (const float*)d_in[3];
    const float* w_out    = (const float*)d_in[4];
    const float* b_out    = (const float*)d_in[5];
    const float* ln_gamma = (const float*)d_in[6];
    const float* ln_beta  = (const float*)d_in[7];
    float* out = (float*)d_out;

    __nv_bfloat16* qkv_bf;   cudaGetSymbolAddress((void**)&qkv_bf,   g_qkv_bf);
    __nv_bfloat16* attn_bf;  cudaGetSymbolAddress((void**)&attn_bf,  g_attn_bf);
    __nv_bfloat16* slots_bf; cudaGetSymbolAddress((void**)&slots_bf, g_slots_bf);
    __nv_bfloat16* win_bf;   cudaGetSymbolAddress((void**)&win_bf,   g_win_bf);
    __nv_bfloat16* wout_bf;  cudaGetSymbolAddress((void**)&wout_bf,  g_wout_bf);

    // 0) convert inputs to bf16 (slots, w_in, w_out)
    {
        const int n0 = N_TOK * D_MODEL, n1 = QKV_W * D_MODEL, n2 = D_MODEL * D_MODEL;
        const int total4 = (n0 + n1 + n2) / 4;
        cvt_bf16_kernel<<<(total4 + 255) / 256, 256>>>(slots, slots_bf, n0,
                                                       w_in, win_bf, n1,
                                                       w_out, wout_bf, n2);
    }
    // 1) QKV projection (bf16 in/out, BK=64 depth-2): qkv = slots @ w_in^T + b_in
    {
        dim3 grid(QKV_W / GBN, N_TOK / GBM);
        gemm_bf16_kernel<<<grid, 256>>>(slots_bf, win_bf, b_in, qkv_bf,
                                        N_TOK, QKV_W, D_MODEL);
    }
    // 2) block-diagonal flash attention (bf16 mma, KT=64, P in registers)
    {
        dim3 grid(N_TOK / QT, H_HEADS);
        flash_attn_kernel<<<grid, 128>>>(qkv_bf, batch_ix, attn_bf);
    }
    // 3) fused out-projection + bias + residual + LayerNorm (BK=64, 512 t)
    {
        const int smem_bytes = G2WORDS * (int)sizeof(uint32_t);  // ~116 KB
        cudaFuncSetAttribute(gemm2_ln_kernel,
                             cudaFuncAttributeMaxDynamicSharedMemorySize, smem_bytes);
        gemm2_ln_kernel<<<N_TOK / G2BM, 512, smem_bytes>>>(attn_bf, wout_bf, b_out, slots,
                                                           ln_gamma, ln_beta, out);
    }
}